// round 14
// baseline (speedup 1.0000x reference)
#include <cuda_runtime.h>
#include <stdint.h>

#define BATCH 64
#define PIX   784
#define DIMS  10000
#define LVLS  256
#define NCLS  10
#define WPAD  320          // words per row: 10 groups x 32 words
#define NGRP  10           // groups of 1024 dims per row
#define EWARPS 10          // encode warps per block (pixel chunks)

#define NROWS      (PIX + LVLS)          // 1040
#define NTASK_PACK (NROWS * NGRP)        // 10400
#define NTASK_IDX  ((BATCH * PIX) / 128) // 392
#define NTASK_ALL  (NTASK_PACK + NTASK_IDX)
#define PACK_BLOCKS 592

// Packed bit layout (PERMUTED, identical for pos / lvl / enc):
//   dim d = g*1024 + i*128 + l*4 + j  <->  word (g*32 + l), bit (i*4 + j)

// ---- scratch (static device globals; zero-init, no allocations) ----
__device__ uint32_t g_pos_bits[PIX  * WPAD];
__device__ uint32_t g_lvl_bits[LVLS * WPAD];
__device__ uint8_t  g_idx[BATCH * PIX];
__device__ float    g_pd[BATCH * NCLS * NGRP];   // per-(b,c,wblock) partial logits
__device__ int      g_arrive[BATCH];             // arrival counters (reset each use)

// 10 pixel chunks: 6x80 + 4x76 (all multiples of 4), sum = 784
__device__ __constant__ int c_start[EWARPS] =
    {0, 80, 160, 240, 320, 400, 480, 556, 632, 708};
__device__ __constant__ int c_len[EWARPS] =
    {80, 80, 80, 80, 80, 80, 76, 76, 76, 76};

// ------------------------------------------------------------------
// K0: grid-stride warp-task pack + idx quant (at its measured ceiling).
// ------------------------------------------------------------------
__global__ void __launch_bounds__(256, 4) pack_all(const float* __restrict__ pos,
                                                   const float* __restrict__ lvl,
                                                   const float* __restrict__ x) {
    int lane  = threadIdx.x & 31;
    int gwarp = (blockIdx.x * 256 + threadIdx.x) >> 5;
    const int nwarps = PACK_BLOCKS * 8;

    for (int task = gwarp; task < NTASK_ALL; task += nwarps) {
        if (task < NTASK_PACK) {
            int row = task / NGRP;
            int g   = task - row * NGRP;

            const float* src;
            uint32_t* dst;
            if (row < PIX) { src = pos + (size_t)row * DIMS; dst = g_pos_bits + row * WPAD; }
            else           { src = lvl + (size_t)(row - PIX) * DIMS; dst = g_lvl_bits + (row - PIX) * WPAD; }

            float4 v[8];
            #pragma unroll
            for (int i = 0; i < 8; i++) {
                int e = g * 1024 + i * 128 + lane * 4;
                v[i] = (e < DIMS) ? *(const float4*)(src + e)
                                  : make_float4(1.0f, 1.0f, 1.0f, 1.0f);
            }

            uint32_t w = 0;
            #pragma unroll
            for (int i = 0; i < 8; i++) {
                uint32_t nib = (__float_as_uint(v[i].x) >> 31)
                             | ((__float_as_uint(v[i].y) >> 31) << 1)
                             | ((__float_as_uint(v[i].z) >> 31) << 2)
                             | ((__float_as_uint(v[i].w) >> 31) << 3);
                w |= nib << (i * 4);
            }
            dst[g * 32 + lane] = w;
        } else {
            int t2 = task - NTASK_PACK;
            int base = t2 * 128 + lane * 4;
            float4 v = *(const float4*)(x + base);
            uchar4 o;
            int i0 = __float2int_rn(v.x * 255.0f); o.x = (uint8_t)max(0, min(255, i0));
            int i1 = __float2int_rn(v.y * 255.0f); o.y = (uint8_t)max(0, min(255, i1));
            int i2 = __float2int_rn(v.z * 255.0f); o.z = (uint8_t)max(0, min(255, i2));
            int i3 = __float2int_rn(v.w * 255.0f); o.w = (uint8_t)max(0, min(255, i3));
            *(uchar4*)(g_idx + base) = o;
        }
    }
}

// fold 4 bound words into a 6-plane CSA counter set (max 63 per column)
__device__ __forceinline__ void acc4(uint32_t* c, uint32_t x0, uint32_t x1,
                                     uint32_t x2, uint32_t x3) {
    uint32_t t0  = x0 ^ x1;
    uint32_t l01 = t0 ^ x2;
    uint32_t h01 = (x0 & x1) | (t0 & x2);
    uint32_t t1 = c[0] ^ l01;
    uint32_t ca = (c[0] & l01) | (t1 & x3);
    c[0] = t1 ^ x3;
    uint32_t t2 = c[1] ^ h01;
    uint32_t cb = (c[1] & h01) | (t2 & ca);
    c[1] = t2 ^ ca;
    uint32_t cr = cb, t;
    t = c[2] & cr; c[2] ^= cr; cr = t;
    t = c[3] & cr; c[3] ^= cr; cr = t;
    t = c[4] & cr; c[4] ^= cr; cr = t;
    c[5] ^= cr;
}

__device__ __forceinline__ void gather_acc(const uint32_t* s_lvl, int lane,
                                           uint32_t i4, const uint32_t* posr,
                                           int q, uint32_t* cnt) {
    uint32_t x0 = s_lvl[((i4      ) & 255u) * 32 + lane] ^ posr[(q * 4 + 0) * WPAD];
    uint32_t x1 = s_lvl[((i4 >>  8) & 255u) * 32 + lane] ^ posr[(q * 4 + 1) * WPAD];
    uint32_t x2 = s_lvl[((i4 >> 16) & 255u) * 32 + lane] ^ posr[(q * 4 + 2) * WPAD];
    uint32_t x3 = s_lvl[((i4 >> 24)       ) * 32 + lane] ^ posr[(q * 4 + 3) * WPAD];
    acc4(cnt, x0, x1, x2, x3);
}

// ------------------------------------------------------------------
// K1: fused bind+bundle + threshold + partial classify + final reduce.
// Grid (10 wblocks, 64 batches), 320 threads (10 warps = 10 pixel chunks)
// -> 6400 warps total (67% occupancy vs previous 54%).
// ------------------------------------------------------------------
__global__ void __launch_bounds__(320, 5) hdc_encode(const float* __restrict__ Wc,
                                                     float* __restrict__ out) {
    __shared__ uint32_t s_lvl[LVLS * 32];      // 32 KB (aliased as s_pl)
    __shared__ uint32_t s_enc[32];
    __shared__ float    s_red[EWARPS][NCLS];
    __shared__ int      s_last;

    int lane   = threadIdx.x & 31;
    int wid    = threadIdx.x >> 5;             // pixel chunk 0..9
    int wblock = blockIdx.x;                   // 0..9
    int b      = blockIdx.y;                   // 0..63
    int w = wblock * 32 + lane;

    for (int l = wid; l < LVLS; l += EWARPS)
        s_lvl[l * 32 + lane] = g_lvl_bits[l * WPAD + w];
    __syncthreads();

    int pstart = c_start[wid];
    int nq     = c_len[wid] >> 2;              // 20 or 19 quads
    const uint8_t*  idxr = g_idx + b * PIX + pstart;        // 4-aligned
    const uint32_t* posr = g_pos_bits + pstart * WPAD + w;

    uint32_t cA[6] = {0, 0, 0, 0, 0, 0};       // even quads (<= 10*4 = 40)
    uint32_t cB[6] = {0, 0, 0, 0, 0, 0};       // odd quads + tail (<= 40)

    int q = 0;
    for (; q + 1 < nq; q += 2) {
        uint32_t ia = *(const uint32_t*)(idxr + q * 4);
        uint32_t ib = *(const uint32_t*)(idxr + q * 4 + 4);
        gather_acc(s_lvl, lane, ia, posr, q,     cA);
        gather_acc(s_lvl, lane, ib, posr, q + 1, cB);
    }
    if (q < nq) {                              // odd tail quad (nq = 19)
        uint32_t it = *(const uint32_t*)(idxr + q * 4);
        gather_acc(s_lvl, lane, it, posr, q, cB);
    }

    // merge A + B -> 7 planes (max 80 < 128)
    uint32_t D[7];
    {
        uint32_t carry = 0;
        #pragma unroll
        for (int i = 0; i < 6; i++) {
            uint32_t t = cA[i] ^ cB[i];
            D[i] = t ^ carry;
            carry = (cA[i] & cB[i]) | (t & carry);
        }
        D[6] = carry;
    }
    __syncthreads();                           // everyone done reading s_lvl

    uint32_t (*s_pl)[7][32] = (uint32_t (*)[7][32])s_lvl;
    #pragma unroll
    for (int i = 0; i < 7; i++) s_pl[wid][i][lane] = D[i];
    __syncthreads();

    if (wid == 0) {
        uint32_t cur[10];
        #pragma unroll
        for (int i = 0; i < 7; i++) cur[i] = s_pl[0][i][lane];
        #pragma unroll
        for (int i = 7; i < 10; i++) cur[i] = 0;

        #pragma unroll
        for (int k = 1; k < EWARPS; k++) {
            uint32_t carry = 0;
            #pragma unroll
            for (int i = 0; i < 7; i++) {
                uint32_t bv = s_pl[k][i][lane];
                uint32_t a  = cur[i];
                uint32_t t  = a ^ bv;
                cur[i] = t ^ carry;
                carry  = (a & bv) | (t & carry);
            }
            #pragma unroll
            for (int i = 7; i < 10; i++) {
                uint32_t a = cur[i];
                cur[i] = a ^ carry;
                carry  = a & carry;
            }
        }

        // cnt >= 392 (0b0110001000) -> enc = -1
        uint32_t gt = 0, eq = 0xffffffffu;
        #pragma unroll
        for (int i = 9; i >= 0; i--) {
            if ((392 >> i) & 1) { eq &= cur[i]; }
            else { gt |= eq & cur[i]; eq &= ~cur[i]; }
        }
        s_enc[lane] = gt | eq;
    }
    __syncthreads();

    // fused partial classify: threads 0..255 cover dims [wblock*1024 + t*4, +4)
    int t4 = threadIdx.x;
    int d  = wblock * 1024 + t4 * 4;
    float acc[NCLS];
    #pragma unroll
    for (int c = 0; c < NCLS; c++) acc[c] = 0.0f;

    if (t4 < 256 && d < DIMS) {
        uint32_t nib = s_enc[t4 & 31] >> (((t4 >> 5) & 7) << 2);
        uint32_t f0 = (nib        & 1u) << 31;
        uint32_t f1 = ((nib >> 1) & 1u) << 31;
        uint32_t f2 = ((nib >> 2) & 1u) << 31;
        uint32_t f3 = ((nib >> 3) & 1u) << 31;
        #pragma unroll
        for (int c = 0; c < NCLS; c++) {
            float4 v = *(const float4*)(Wc + (size_t)c * DIMS + d);
            float s01 = __uint_as_float(__float_as_uint(v.x) ^ f0)
                      + __uint_as_float(__float_as_uint(v.y) ^ f1);
            float s23 = __uint_as_float(__float_as_uint(v.z) ^ f2)
                      + __uint_as_float(__float_as_uint(v.w) ^ f3);
            acc[c] = s01 + s23;
        }
    }

    #pragma unroll
    for (int c = 0; c < NCLS; c++) {
        float v = acc[c];
        #pragma unroll
        for (int off = 16; off > 0; off >>= 1)
            v += __shfl_down_sync(0xffffffffu, v, off);
        if (lane == 0) s_red[wid][c] = v;
    }
    __syncthreads();

    if (wid == 0 && lane < NCLS) {
        float s = 0.0f;
        #pragma unroll
        for (int k = 0; k < EWARPS; k++) s += s_red[k][lane];
        g_pd[(b * NCLS + lane) * NGRP + wblock] = s;
    }
    __syncthreads();

    // --- last-block reduction for batch b ---
    if (threadIdx.x == 0) {
        __threadfence();
        int old = atomicAdd(&g_arrive[b], 1);
        s_last = (old == NGRP - 1);
    }
    __syncthreads();

    if (s_last) {
        if (threadIdx.x == 0) __threadfence();
        __syncthreads();
        if (wid == 0 && lane < NCLS) {
            const float* p = g_pd + (b * NCLS + lane) * NGRP;
            float s = 0.0f;
            #pragma unroll
            for (int i = 0; i < NGRP; i++) s += p[i];   // fixed order -> deterministic
            out[b * NCLS + lane] = s;
        }
        if (threadIdx.x == 0) g_arrive[b] = 0;
    }
}

// ------------------------------------------------------------------
extern "C" void kernel_launch(void* const* d_in, const int* in_sizes, int n_in,
                              void* d_out, int out_size) {
    const float* x   = (const float*)d_in[0];   // [64,28,28]
    const float* pos = (const float*)d_in[1];   // [784,10000]
    const float* lvl = (const float*)d_in[2];   // [256,10000]
    const float* cw  = (const float*)d_in[3];   // [10,10000]
    float* out = (float*)d_out;                 // [64,10]

    pack_all<<<PACK_BLOCKS, 256>>>(pos, lvl, x);
    hdc_encode<<<dim3(NGRP, BATCH), 320>>>(cw, out);
}

// round 15
// speedup vs baseline: 1.0767x; 1.0767x over previous
#include <cuda_runtime.h>
#include <stdint.h>

#define BATCH 64
#define PIX   784
#define DIMS  10000
#define LVLS  256
#define NCLS  10
#define WPAD  320          // words per row: 10 groups x 32 words
#define NGRP  10           // groups of 1024 dims per row

#define NROWS      (PIX + LVLS)          // 1040
#define NTASK_PACK (NROWS * NGRP)        // 10400
#define NTASK_IDX  ((BATCH * PIX) / 128) // 392
#define NTASK_ALL  (NTASK_PACK + NTASK_IDX)
#define PACK_BLOCKS 592

// Packed bit layout (PERMUTED, identical for pos / lvl / enc):
//   dim d = g*1024 + i*128 + l*4 + j  <->  word (g*32 + l), bit (i*4 + j)

// ---- scratch (static device globals; zero-init, no allocations) ----
__device__ uint32_t g_pos_bits[PIX  * WPAD];
__device__ uint32_t g_lvl_bits[LVLS * WPAD];
__device__ uint8_t  g_idx[BATCH * PIX];
__device__ float    g_pd[BATCH * NCLS * NGRP];   // per-(b,c,wblock) partial logits
__device__ int      g_arrive[BATCH];             // arrival counters (reset each use)

// pixel chunk starts (all multiples of 4) and lengths {100x4, 96x4}
__device__ __constant__ int c_start[8] = {0, 100, 200, 300, 400, 496, 592, 688};
__device__ __constant__ int c_len[8]   = {100, 100, 100, 100, 96, 96, 96, 96};

// explicit 3-input LOP3s: CSA = exactly 2 ops
__device__ __forceinline__ uint32_t xor3(uint32_t a, uint32_t b, uint32_t c) {
    uint32_t r;
    asm("lop3.b32 %0, %1, %2, %3, 0x96;" : "=r"(r) : "r"(a), "r"(b), "r"(c));
    return r;
}
__device__ __forceinline__ uint32_t maj3(uint32_t a, uint32_t b, uint32_t c) {
    uint32_t r;
    asm("lop3.b32 %0, %1, %2, %3, 0xE8;" : "=r"(r) : "r"(a), "r"(b), "r"(c));
    return r;
}

// ------------------------------------------------------------------
// K0: grid-stride warp-task pack + idx quant (at its measured ceiling).
// ------------------------------------------------------------------
__global__ void __launch_bounds__(256, 4) pack_all(const float* __restrict__ pos,
                                                   const float* __restrict__ lvl,
                                                   const float* __restrict__ x) {
    int lane  = threadIdx.x & 31;
    int gwarp = (blockIdx.x * 256 + threadIdx.x) >> 5;
    const int nwarps = PACK_BLOCKS * 8;

    for (int task = gwarp; task < NTASK_ALL; task += nwarps) {
        if (task < NTASK_PACK) {
            int row = task / NGRP;
            int g   = task - row * NGRP;

            const float* src;
            uint32_t* dst;
            if (row < PIX) { src = pos + (size_t)row * DIMS; dst = g_pos_bits + row * WPAD; }
            else           { src = lvl + (size_t)(row - PIX) * DIMS; dst = g_lvl_bits + (row - PIX) * WPAD; }

            float4 v[8];
            #pragma unroll
            for (int i = 0; i < 8; i++) {
                int e = g * 1024 + i * 128 + lane * 4;
                v[i] = (e < DIMS) ? *(const float4*)(src + e)
                                  : make_float4(1.0f, 1.0f, 1.0f, 1.0f);
            }

            uint32_t w = 0;
            #pragma unroll
            for (int i = 0; i < 8; i++) {
                uint32_t nib = (__float_as_uint(v[i].x) >> 31)
                             | ((__float_as_uint(v[i].y) >> 31) << 1)
                             | ((__float_as_uint(v[i].z) >> 31) << 2)
                             | ((__float_as_uint(v[i].w) >> 31) << 3);
                w |= nib << (i * 4);
            }
            dst[g * 32 + lane] = w;
        } else {
            int t2 = task - NTASK_PACK;
            int base = t2 * 128 + lane * 4;
            float4 v = *(const float4*)(x + base);
            uchar4 o;
            int i0 = __float2int_rn(v.x * 255.0f); o.x = (uint8_t)max(0, min(255, i0));
            int i1 = __float2int_rn(v.y * 255.0f); o.y = (uint8_t)max(0, min(255, i1));
            int i2 = __float2int_rn(v.z * 255.0f); o.z = (uint8_t)max(0, min(255, i2));
            int i3 = __float2int_rn(v.w * 255.0f); o.w = (uint8_t)max(0, min(255, i3));
            *(uchar4*)(g_idx + base) = o;
        }
    }
}

// ------------------------------------------------------------------
// K1: fused bind+bundle + threshold + partial classify + final reduce.
// Grid (10 wblocks, 64 batches), 256 threads. Warp = one pixel chunk.
// Quad-PAIR folding with explicit XOR3/MAJ3 CSAs and deferred carries:
// 29 logic ops per 8 pixels (vs ~50 before).
// ------------------------------------------------------------------
__global__ void __launch_bounds__(256) hdc_encode(const float* __restrict__ Wc,
                                                  float* __restrict__ out) {
    __shared__ uint32_t s_lvl[LVLS * 32];      // 32 KB (aliased as s_pl)
    __shared__ uint32_t s_enc[32];
    __shared__ float    s_red[8][NCLS];
    __shared__ int      s_last;

    int lane   = threadIdx.x & 31;
    int wid    = threadIdx.x >> 5;             // pixel chunk 0..7
    int wblock = blockIdx.x;                   // 0..9
    int b      = blockIdx.y;                   // 0..63
    int w = wblock * 32 + lane;

    for (int l = wid; l < LVLS; l += 8)
        s_lvl[l * 32 + lane] = g_lvl_bits[l * WPAD + w];
    __syncthreads();

    int pstart = c_start[wid];
    int nq     = c_len[wid] >> 2;              // 25 or 24 quads
    const uint8_t*  idxr = g_idx + b * PIX + pstart;        // 4-aligned
    const uint32_t* posr = g_pos_bits + pstart * WPAD + w;

    // single 7-plane counter (max 100 per column < 128)
    uint32_t c0 = 0, c1 = 0, c2 = 0, c3 = 0, c4 = 0, c5 = 0, c6 = 0;

    int q = 0;
    for (; q + 1 < nq; q += 2) {
        uint32_t ia = *(const uint32_t*)(idxr + q * 4);
        uint32_t ib = *(const uint32_t*)(idxr + q * 4 + 4);

        uint32_t x0 = s_lvl[((ia      ) & 255u) * 32 + lane] ^ posr[(q * 4 + 0) * WPAD];
        uint32_t x1 = s_lvl[((ia >>  8) & 255u) * 32 + lane] ^ posr[(q * 4 + 1) * WPAD];
        uint32_t x2 = s_lvl[((ia >> 16) & 255u) * 32 + lane] ^ posr[(q * 4 + 2) * WPAD];
        uint32_t x3 = s_lvl[((ia >> 24)       ) * 32 + lane] ^ posr[(q * 4 + 3) * WPAD];
        uint32_t x4 = s_lvl[((ib      ) & 255u) * 32 + lane] ^ posr[(q * 4 + 4) * WPAD];
        uint32_t x5 = s_lvl[((ib >>  8) & 255u) * 32 + lane] ^ posr[(q * 4 + 5) * WPAD];
        uint32_t x6 = s_lvl[((ib >> 16) & 255u) * 32 + lane] ^ posr[(q * 4 + 6) * WPAD];
        uint32_t x7 = s_lvl[((ib >> 24)       ) * 32 + lane] ^ posr[(q * 4 + 7) * WPAD];

        // quad A: (sA weight1, cA weight2)
        uint32_t sA = xor3(x0, x1, x2);
        uint32_t cA = maj3(x0, x1, x2);
        uint32_t t0 = xor3(c0, sA, x3);        // ones after A
        uint32_t kA = maj3(c0, sA, x3);        // weight-2 carry
        // quad B
        uint32_t sB = xor3(x4, x5, x6);
        uint32_t cB = maj3(x4, x5, x6);
        uint32_t kB = maj3(t0, sB, x7);        // weight-2 carry
        c0 = xor3(t0, sB, x7);
        // weight-2 inputs {cA, cB, kA, kB} + plane c1
        uint32_t s1 = xor3(cA, cB, kA);
        uint32_t k1 = maj3(cA, cB, kA);        // weight-4
        uint32_t k2 = maj3(c1, s1, kB);        // weight-4
        c1 = xor3(c1, s1, kB);
        // weight-4 inputs {k1, k2} + plane c2
        uint32_t k3 = maj3(c2, k1, k2);        // weight-8
        c2 = xor3(c2, k1, k2);
        // ripple k3 through c3..c6
        uint32_t t;
        t = c3 & k3; c3 ^= k3; k3 = t;
        t = c4 & k3; c4 ^= k3; k3 = t;
        t = c5 & k3; c5 ^= k3; k3 = t;
        c6 ^= k3;
    }
    if (q < nq) {                              // odd tail quad (nq = 25)
        uint32_t ia = *(const uint32_t*)(idxr + q * 4);
        uint32_t x0 = s_lvl[((ia      ) & 255u) * 32 + lane] ^ posr[(q * 4 + 0) * WPAD];
        uint32_t x1 = s_lvl[((ia >>  8) & 255u) * 32 + lane] ^ posr[(q * 4 + 1) * WPAD];
        uint32_t x2 = s_lvl[((ia >> 16) & 255u) * 32 + lane] ^ posr[(q * 4 + 2) * WPAD];
        uint32_t x3 = s_lvl[((ia >> 24)       ) * 32 + lane] ^ posr[(q * 4 + 3) * WPAD];

        uint32_t sA = xor3(x0, x1, x2);
        uint32_t cA = maj3(x0, x1, x2);
        uint32_t kA = maj3(c0, sA, x3);
        c0 = xor3(c0, sA, x3);
        uint32_t k1 = maj3(c1, cA, kA);
        c1 = xor3(c1, cA, kA);
        uint32_t t;
        t = c2 & k1; c2 ^= k1; k1 = t;
        t = c3 & k1; c3 ^= k1; k1 = t;
        t = c4 & k1; c4 ^= k1; k1 = t;
        t = c5 & k1; c5 ^= k1; k1 = t;
        c6 ^= k1;
    }
    __syncthreads();                           // everyone done reading s_lvl

    uint32_t (*s_pl)[7][32] = (uint32_t (*)[7][32])s_lvl;
    s_pl[wid][0][lane] = c0; s_pl[wid][1][lane] = c1;
    s_pl[wid][2][lane] = c2; s_pl[wid][3][lane] = c3;
    s_pl[wid][4][lane] = c4; s_pl[wid][5][lane] = c5;
    s_pl[wid][6][lane] = c6;
    __syncthreads();

    if (wid == 0) {
        uint32_t cur[10];
        #pragma unroll
        for (int i = 0; i < 7; i++) cur[i] = s_pl[0][i][lane];
        #pragma unroll
        for (int i = 7; i < 10; i++) cur[i] = 0;

        #pragma unroll
        for (int k = 1; k < 8; k++) {
            uint32_t carry = 0;
            #pragma unroll
            for (int i = 0; i < 7; i++) {
                uint32_t bv = s_pl[k][i][lane];
                uint32_t a  = cur[i];
                uint32_t t  = a ^ bv;
                cur[i] = t ^ carry;
                carry  = maj3(a, bv, carry);
            }
            #pragma unroll
            for (int i = 7; i < 10; i++) {
                uint32_t a = cur[i];
                cur[i] = a ^ carry;
                carry  = a & carry;
            }
        }

        // cnt >= 392 (0b0110001000) -> enc = -1
        uint32_t gt = 0, eq = 0xffffffffu;
        #pragma unroll
        for (int i = 9; i >= 0; i--) {
            if ((392 >> i) & 1) { eq &= cur[i]; }
            else { gt |= eq & cur[i]; eq &= ~cur[i]; }
        }
        s_enc[lane] = gt | eq;
    }
    __syncthreads();

    // fused partial classify: thread t covers dims [wblock*1024 + t*4, +4)
    int t4 = threadIdx.x;
    int d  = wblock * 1024 + t4 * 4;
    float acc[NCLS];
    #pragma unroll
    for (int c = 0; c < NCLS; c++) acc[c] = 0.0f;

    if (d < DIMS) {
        uint32_t nib = s_enc[t4 & 31] >> (((t4 >> 5) & 7) << 2);
        uint32_t f0 = (nib        & 1u) << 31;
        uint32_t f1 = ((nib >> 1) & 1u) << 31;
        uint32_t f2 = ((nib >> 2) & 1u) << 31;
        uint32_t f3 = ((nib >> 3) & 1u) << 31;
        #pragma unroll
        for (int c = 0; c < NCLS; c++) {
            float4 v = *(const float4*)(Wc + (size_t)c * DIMS + d);
            float s01 = __uint_as_float(__float_as_uint(v.x) ^ f0)
                      + __uint_as_float(__float_as_uint(v.y) ^ f1);
            float s23 = __uint_as_float(__float_as_uint(v.z) ^ f2)
                      + __uint_as_float(__float_as_uint(v.w) ^ f3);
            acc[c] = s01 + s23;
        }
    }

    #pragma unroll
    for (int c = 0; c < NCLS; c++) {
        float v = acc[c];
        #pragma unroll
        for (int off = 16; off > 0; off >>= 1)
            v += __shfl_down_sync(0xffffffffu, v, off);
        if (lane == 0) s_red[wid][c] = v;
    }
    __syncthreads();

    if (wid == 0 && lane < NCLS) {
        float s = 0.0f;
        #pragma unroll
        for (int k = 0; k < 8; k++) s += s_red[k][lane];
        g_pd[(b * NCLS + lane) * NGRP + wblock] = s;
    }
    __syncthreads();

    // --- last-block reduction for batch b ---
    if (threadIdx.x == 0) {
        __threadfence();
        int old = atomicAdd(&g_arrive[b], 1);
        s_last = (old == NGRP - 1);
    }
    __syncthreads();

    if (s_last) {
        if (threadIdx.x == 0) __threadfence();
        __syncthreads();
        if (wid == 0 && lane < NCLS) {
            const float* p = g_pd + (b * NCLS + lane) * NGRP;
            float s = 0.0f;
            #pragma unroll
            for (int i = 0; i < NGRP; i++) s += p[i];   // fixed order -> deterministic
            out[b * NCLS + lane] = s;
        }
        if (threadIdx.x == 0) g_arrive[b] = 0;
    }
}

// ------------------------------------------------------------------
extern "C" void kernel_launch(void* const* d_in, const int* in_sizes, int n_in,
                              void* d_out, int out_size) {
    const float* x   = (const float*)d_in[0];   // [64,28,28]
    const float* pos = (const float*)d_in[1];   // [784,10000]
    const float* lvl = (const float*)d_in[2];   // [256,10000]
    const float* cw  = (const float*)d_in[3];   // [10,10000]
    float* out = (float*)d_out;                 // [64,10]

    pack_all<<<PACK_BLOCKS, 256>>>(pos, lvl, x);
    hdc_encode<<<dim3(NGRP, BATCH), 256>>>(cw, out);
}

// round 16
// speedup vs baseline: 1.1633x; 1.0804x over previous
#include <cuda_runtime.h>
#include <stdint.h>

#define BATCH 64
#define PIX   784
#define DIMS  10000
#define LVLS  256
#define NCLS  10
#define WPAD  320          // words per row: 10 groups x 32 words
#define NGRP  10           // groups of 1024 dims per row

#define NROWS      (PIX + LVLS)          // 1040
#define NTASK_PACK (NROWS * NGRP)        // 10400
#define NTASK_IDX  ((BATCH * PIX) / 128) // 392
#define NTASK_ALL  (NTASK_PACK + NTASK_IDX)
#define PACK_BLOCKS 592

// Packed bit layout (PERMUTED, identical for pos / lvl / enc):
//   dim d = g*1024 + i*128 + l*4 + j  <->  word (g*32 + l), bit (i*4 + j)

// ---- scratch (static device globals; zero-init, no allocations) ----
__device__ uint32_t g_pos_bits[PIX  * WPAD];
__device__ uint32_t g_lvl_bits[LVLS * WPAD];
__device__ uint8_t  g_idx[BATCH * PIX];
__device__ float    g_pd[BATCH * NCLS * NGRP];   // per-(b,c,wblock) partial logits
__device__ int      g_arrive[BATCH];             // arrival counters (reset each use)

// pixel chunk starts (all multiples of 4) and lengths {100x4, 96x4}
__device__ __constant__ int c_start[8] = {0, 100, 200, 300, 400, 496, 592, 688};
__device__ __constant__ int c_len[8]   = {100, 100, 100, 100, 96, 96, 96, 96};

// ------------------------------------------------------------------
// K0: grid-stride warp-task pack + idx quant.
// Streaming (__ldcs) reads: single-use data, don't pollute L1.
// ------------------------------------------------------------------
__global__ void __launch_bounds__(256, 4) pack_all(const float* __restrict__ pos,
                                                   const float* __restrict__ lvl,
                                                   const float* __restrict__ x) {
    int lane  = threadIdx.x & 31;
    int gwarp = (blockIdx.x * 256 + threadIdx.x) >> 5;
    const int nwarps = PACK_BLOCKS * 8;

    for (int task = gwarp; task < NTASK_ALL; task += nwarps) {
        if (task < NTASK_PACK) {
            int row = task / NGRP;
            int g   = task - row * NGRP;

            const float* src;
            uint32_t* dst;
            if (row < PIX) { src = pos + (size_t)row * DIMS; dst = g_pos_bits + row * WPAD; }
            else           { src = lvl + (size_t)(row - PIX) * DIMS; dst = g_lvl_bits + (row - PIX) * WPAD; }

            float4 v[8];
            #pragma unroll
            for (int i = 0; i < 8; i++) {
                int e = g * 1024 + i * 128 + lane * 4;
                v[i] = (e < DIMS) ? __ldcs((const float4*)(src + e))
                                  : make_float4(1.0f, 1.0f, 1.0f, 1.0f);
            }

            uint32_t w = 0;
            #pragma unroll
            for (int i = 0; i < 8; i++) {
                uint32_t nib = (__float_as_uint(v[i].x) >> 31)
                             | ((__float_as_uint(v[i].y) >> 31) << 1)
                             | ((__float_as_uint(v[i].z) >> 31) << 2)
                             | ((__float_as_uint(v[i].w) >> 31) << 3);
                w |= nib << (i * 4);
            }
            dst[g * 32 + lane] = w;
        } else {
            int t2 = task - NTASK_PACK;
            int base = t2 * 128 + lane * 4;
            float4 v = __ldcs((const float4*)(x + base));
            uchar4 o;
            int i0 = __float2int_rn(v.x * 255.0f); o.x = (uint8_t)max(0, min(255, i0));
            int i1 = __float2int_rn(v.y * 255.0f); o.y = (uint8_t)max(0, min(255, i1));
            int i2 = __float2int_rn(v.z * 255.0f); o.z = (uint8_t)max(0, min(255, i2));
            int i3 = __float2int_rn(v.w * 255.0f); o.w = (uint8_t)max(0, min(255, i3));
            *(uchar4*)(g_idx + base) = o;
        }
    }
}

// fold 4 bound words into a 6-plane CSA counter set (max 63 per column)
__device__ __forceinline__ void acc4(uint32_t* c, uint32_t x0, uint32_t x1,
                                     uint32_t x2, uint32_t x3) {
    uint32_t t0  = x0 ^ x1;
    uint32_t l01 = t0 ^ x2;
    uint32_t h01 = (x0 & x1) | (t0 & x2);
    uint32_t t1 = c[0] ^ l01;
    uint32_t ca = (c[0] & l01) | (t1 & x3);
    c[0] = t1 ^ x3;
    uint32_t t2 = c[1] ^ h01;
    uint32_t cb = (c[1] & h01) | (t2 & ca);
    c[1] = t2 ^ ca;
    uint32_t cr = cb, t;
    t = c[2] & cr; c[2] ^= cr; cr = t;
    t = c[3] & cr; c[3] ^= cr; cr = t;
    t = c[4] & cr; c[4] ^= cr; cr = t;
    c[5] ^= cr;
}

// ------------------------------------------------------------------
// K1: fused bind+bundle + threshold + partial classify + final reduce.
// Grid (10 wblocks, 64 batches), 256 threads. Warp = one pixel chunk.
// DUAL counter sets (even/odd quads) -> two independent CSA chains.
// (Proven R12 structure: 25.09us wall.)
// ------------------------------------------------------------------
__global__ void __launch_bounds__(256) hdc_encode(const float* __restrict__ Wc,
                                                  float* __restrict__ out) {
    __shared__ uint32_t s_lvl[LVLS * 32];      // 32 KB (aliased as s_pl)
    __shared__ uint32_t s_enc[32];
    __shared__ float    s_red[8][NCLS];
    __shared__ int      s_last;

    int lane   = threadIdx.x & 31;
    int wid    = threadIdx.x >> 5;             // pixel chunk 0..7
    int wblock = blockIdx.x;                   // 0..9
    int b      = blockIdx.y;                   // 0..63
    int w = wblock * 32 + lane;

    for (int l = wid; l < LVLS; l += 8)
        s_lvl[l * 32 + lane] = g_lvl_bits[l * WPAD + w];
    __syncthreads();

    int pstart = c_start[wid];
    int nq     = c_len[wid] >> 2;              // 25 or 24 quads
    const uint8_t*  idxr = g_idx + b * PIX + pstart;        // 4-aligned
    const uint32_t* posr = g_pos_bits + pstart * WPAD + w;

    uint32_t cA[6] = {0, 0, 0, 0, 0, 0};       // even quads (<= 13*4 = 52)
    uint32_t cB[6] = {0, 0, 0, 0, 0, 0};       // odd  quads (<= 12*4 = 48)

    int q = 0;
    for (; q + 1 < nq; q += 2) {
        // quad q -> A
        uint32_t ia = *(const uint32_t*)(idxr + q * 4);
        uint32_t a0 = s_lvl[((ia      ) & 255u) * 32 + lane] ^ posr[(q * 4 + 0) * WPAD];
        uint32_t a1 = s_lvl[((ia >>  8) & 255u) * 32 + lane] ^ posr[(q * 4 + 1) * WPAD];
        uint32_t a2 = s_lvl[((ia >> 16) & 255u) * 32 + lane] ^ posr[(q * 4 + 2) * WPAD];
        uint32_t a3 = s_lvl[((ia >> 24)       ) * 32 + lane] ^ posr[(q * 4 + 3) * WPAD];
        // quad q+1 -> B (independent chain)
        uint32_t ib = *(const uint32_t*)(idxr + q * 4 + 4);
        uint32_t b0 = s_lvl[((ib      ) & 255u) * 32 + lane] ^ posr[(q * 4 + 4) * WPAD];
        uint32_t b1 = s_lvl[((ib >>  8) & 255u) * 32 + lane] ^ posr[(q * 4 + 5) * WPAD];
        uint32_t b2 = s_lvl[((ib >> 16) & 255u) * 32 + lane] ^ posr[(q * 4 + 6) * WPAD];
        uint32_t b3 = s_lvl[((ib >> 24)       ) * 32 + lane] ^ posr[(q * 4 + 7) * WPAD];

        acc4(cA, a0, a1, a2, a3);
        acc4(cB, b0, b1, b2, b3);
    }
    if (q < nq) {                              // odd tail -> A
        uint32_t ia = *(const uint32_t*)(idxr + q * 4);
        uint32_t a0 = s_lvl[((ia      ) & 255u) * 32 + lane] ^ posr[(q * 4 + 0) * WPAD];
        uint32_t a1 = s_lvl[((ia >>  8) & 255u) * 32 + lane] ^ posr[(q * 4 + 1) * WPAD];
        uint32_t a2 = s_lvl[((ia >> 16) & 255u) * 32 + lane] ^ posr[(q * 4 + 2) * WPAD];
        uint32_t a3 = s_lvl[((ia >> 24)       ) * 32 + lane] ^ posr[(q * 4 + 3) * WPAD];
        acc4(cA, a0, a1, a2, a3);
    }

    // merge A + B -> 7 planes (max 100 < 128)
    uint32_t D[7];
    {
        uint32_t carry = 0;
        #pragma unroll
        for (int i = 0; i < 6; i++) {
            uint32_t t = cA[i] ^ cB[i];
            D[i] = t ^ carry;
            carry = (cA[i] & cB[i]) | (t & carry);
        }
        D[6] = carry;
    }
    __syncthreads();                           // everyone done reading s_lvl

    uint32_t (*s_pl)[7][32] = (uint32_t (*)[7][32])s_lvl;
    #pragma unroll
    for (int i = 0; i < 7; i++) s_pl[wid][i][lane] = D[i];
    __syncthreads();

    if (wid == 0) {
        uint32_t cur[10];
        #pragma unroll
        for (int i = 0; i < 7; i++) cur[i] = s_pl[0][i][lane];
        #pragma unroll
        for (int i = 7; i < 10; i++) cur[i] = 0;

        #pragma unroll
        for (int k = 1; k < 8; k++) {
            uint32_t carry = 0;
            #pragma unroll
            for (int i = 0; i < 7; i++) {
                uint32_t bv = s_pl[k][i][lane];
                uint32_t a  = cur[i];
                uint32_t t  = a ^ bv;
                cur[i] = t ^ carry;
                carry  = (a & bv) | (t & carry);
            }
            #pragma unroll
            for (int i = 7; i < 10; i++) {
                uint32_t a = cur[i];
                cur[i] = a ^ carry;
                carry  = a & carry;
            }
        }

        // cnt >= 392 (0b0110001000) -> enc = -1
        uint32_t gt = 0, eq = 0xffffffffu;
        #pragma unroll
        for (int i = 9; i >= 0; i--) {
            if ((392 >> i) & 1) { eq &= cur[i]; }
            else { gt |= eq & cur[i]; eq &= ~cur[i]; }
        }
        s_enc[lane] = gt | eq;
    }
    __syncthreads();

    // fused partial classify: thread t covers dims [wblock*1024 + t*4, +4)
    int t4 = threadIdx.x;
    int d  = wblock * 1024 + t4 * 4;
    float acc[NCLS];
    #pragma unroll
    for (int c = 0; c < NCLS; c++) acc[c] = 0.0f;

    if (d < DIMS) {
        uint32_t nib = s_enc[t4 & 31] >> (((t4 >> 5) & 7) << 2);
        uint32_t f0 = (nib        & 1u) << 31;
        uint32_t f1 = ((nib >> 1) & 1u) << 31;
        uint32_t f2 = ((nib >> 2) & 1u) << 31;
        uint32_t f3 = ((nib >> 3) & 1u) << 31;
        #pragma unroll
        for (int c = 0; c < NCLS; c++) {
            float4 v = *(const float4*)(Wc + (size_t)c * DIMS + d);
            float s01 = __uint_as_float(__float_as_uint(v.x) ^ f0)
                      + __uint_as_float(__float_as_uint(v.y) ^ f1);
            float s23 = __uint_as_float(__float_as_uint(v.z) ^ f2)
                      + __uint_as_float(__float_as_uint(v.w) ^ f3);
            acc[c] = s01 + s23;
        }
    }

    #pragma unroll
    for (int c = 0; c < NCLS; c++) {
        float v = acc[c];
        #pragma unroll
        for (int off = 16; off > 0; off >>= 1)
            v += __shfl_down_sync(0xffffffffu, v, off);
        if (lane == 0) s_red[wid][c] = v;
    }
    __syncthreads();

    if (wid == 0 && lane < NCLS) {
        float s = 0.0f;
        #pragma unroll
        for (int k = 0; k < 8; k++) s += s_red[k][lane];
        g_pd[(b * NCLS + lane) * NGRP + wblock] = s;
    }
    __syncthreads();

    // --- last-block reduction for batch b ---
    if (threadIdx.x == 0) {
        __threadfence();
        int old = atomicAdd(&g_arrive[b], 1);
        s_last = (old == NGRP - 1);
    }
    __syncthreads();

    if (s_last) {
        if (threadIdx.x == 0) __threadfence();
        __syncthreads();
        if (wid == 0 && lane < NCLS) {
            const float* p = g_pd + (b * NCLS + lane) * NGRP;
            float s = 0.0f;
            #pragma unroll
            for (int i = 0; i < NGRP; i++) s += p[i];   // fixed order -> deterministic
            out[b * NCLS + lane] = s;
        }
        if (threadIdx.x == 0) g_arrive[b] = 0;
    }
}

// ------------------------------------------------------------------
extern "C" void kernel_launch(void* const* d_in, const int* in_sizes, int n_in,
                              void* d_out, int out_size) {
    const float* x   = (const float*)d_in[0];   // [64,28,28]
    const float* pos = (const float*)d_in[1];   // [784,10000]
    const float* lvl = (const float*)d_in[2];   // [256,10000]
    const float* cw  = (const float*)d_in[3];   // [10,10000]
    float* out = (float*)d_out;                 // [64,10]

    pack_all<<<PACK_BLOCKS, 256>>>(pos, lvl, x);
    hdc_encode<<<dim3(NGRP, BATCH), 256>>>(cw, out);
}